// round 7
// baseline (speedup 1.0000x reference)
#include <cuda_runtime.h>
#include <cuda_bf16.h>
#include <math.h>

#define BB 16
#define PP 19248
#define NOBJ 32
#define NC 81
#define POS_TH 0.5f
#define NEG_TH 0.4f

__device__ float              g_negval[BB * PP];
__device__ unsigned long long g_ovgt[BB * PP];     // (ov_bits << 32) | gt_idx
__device__ unsigned long long g_bestkey[BB * NOBJ];
__device__ float g_loss_l;
__device__ float g_loss_c;
__device__ int   g_npos[BB];
__device__ int   g_total_pos;
__device__ int   g_done;

// monotone float->uint key (ascending order preserved, handles negatives)
__device__ __forceinline__ unsigned fkey(float f) {
    unsigned u = __float_as_uint(f);
    return u ^ (((unsigned)((int)u >> 31)) | 0x80000000u);
}
__device__ __forceinline__ float fkey_inv(unsigned k) {
    unsigned mask = (k >> 31) ? 0x80000000u : 0xFFFFFFFFu;
    return __uint_as_float(k ^ mask);
}

// -------- Kernel 1: IoU pass. one warp handles 8 priors; lane n = gt n --------
__global__ void __launch_bounds__(256) iou_kernel(const float* __restrict__ priors,
                                                  const float* __restrict__ gt_boxes) {
    const int b = blockIdx.y;
    const int warp = threadIdx.x >> 5;
    const int lane = threadIdx.x & 31;

    __shared__ float4             sgt[NOBJ];
    __shared__ unsigned long long skey[NOBJ];
    if (threadIdx.x < NOBJ) {
        sgt[threadIdx.x]  = ((const float4*)gt_boxes)[b * NOBJ + threadIdx.x];
        skey[threadIdx.x] = 0ull;
    }
    __syncthreads();

    float4 g = sgt[lane];
    float area_g = (g.z - g.x) * (g.w - g.y);
    unsigned long long mykey = 0ull;
    unsigned long long myres = 0ull;

    int base = blockIdx.x * 64 + warp * 8;
#pragma unroll
    for (int k = 0; k < 8; k++) {
        int p = base + k;
        if (p >= PP) break;
        float4 pr = ((const float4*)priors)[p];
        float px1 = pr.x - pr.z * 0.5f, py1 = pr.y - pr.w * 0.5f;
        float px2 = pr.x + pr.z * 0.5f, py2 = pr.y + pr.w * 0.5f;
        float area_p = (px2 - px1) * (py2 - py1);

        float lx = fmaxf(g.x, px1), ly = fmaxf(g.y, py1);
        float rx = fminf(g.z, px2), ry = fminf(g.w, py2);
        float w = fmaxf(rx - lx, 0.f), h = fmaxf(ry - ly, 0.f);
        float inter = w * h;
        float ov = inter / (area_g + area_p - inter);   // IEEE div, matches ref

        // per-gt best prior: max ov, tie -> lowest p
        unsigned long long key =
            ((unsigned long long)__float_as_uint(ov) << 32) |
            (unsigned long long)(0xFFFFFFFFu - (unsigned)p);
        mykey = (key > mykey) ? key : mykey;

        // per-prior best gt: max ov, tie -> lowest gt index (ov >= 0 so
        // uint order == float order; ffs of ballot = lowest lane)
        unsigned ovb = __float_as_uint(ov);
        unsigned umax = __reduce_max_sync(0xffffffffu, ovb);
        unsigned bal = __ballot_sync(0xffffffffu, ovb == umax);
        if (lane == k)  // results are warp-uniform; lane k keeps prior k's
            myres = ((unsigned long long)umax << 32) |
                    (unsigned long long)(__ffs(bal) - 1);
    }
    if (lane < 8 && base + lane < PP)
        g_ovgt[(size_t)b * PP + base + lane] = myres;   // coalesced 64B burst

    atomicMax(&skey[lane], mykey);
    __syncthreads();
    if (threadIdx.x < NOBJ)
        atomicMax(&g_bestkey[b * NOBJ + threadIdx.x], skey[threadIdx.x]);
}

// -------- Kernel 2: NLL + match resolution + loc loss (direct global reads) --
#define NLLW 16   // warps per block, PP = 16 * 1203 exactly

__global__ void __launch_bounds__(512) nll_kernel(
        const float* __restrict__ loc_data,
        const float* __restrict__ conf_data,
        const float* __restrict__ priors,
        const float* __restrict__ gt_boxes,
        const int*   __restrict__ gt_labels) {
    const int b = blockIdx.y;
    const int warp = threadIdx.x >> 5;
    const int lane = threadIdx.x & 31;
    const int p = blockIdx.x * NLLW + warp;

    __shared__ float4 sgt[NOBJ];
    __shared__ int    slab[NOBJ];
    __shared__ int    sbp[NOBJ];
    __shared__ float  snv[NLLW];
    if (threadIdx.x < NOBJ) {
        sgt[threadIdx.x]  = ((const float4*)gt_boxes)[b * NOBJ + threadIdx.x];
        slab[threadIdx.x] = gt_labels[b * NOBJ + threadIdx.x];
        unsigned long long k = g_bestkey[b * NOBJ + threadIdx.x];
        sbp[threadIdx.x] = (int)(0xFFFFFFFFu - (unsigned)(k & 0xFFFFFFFFull));
    }

    // kick off match-result load early (lane 0 only)
    unsigned long long og = 0ull;
    if (lane == 0) og = g_ovgt[(size_t)b * PP + p];

    // direct coalesced reads of this prior's 81 logits
    const float* row = conf_data + ((size_t)b * PP + p) * NC;
    float v0 = row[lane];
    float v1 = row[lane + 32];
    float v2 = (lane < NC - 64) ? row[lane + 64] : -INFINITY;
    __syncthreads();

    // warp max via monotone-uint hardware reduce
    unsigned km = fkey(fmaxf(fmaxf(v0, v1), v2));
    km = __reduce_max_sync(0xffffffffu, km);
    float m = fkey_inv(km);

    float s = __expf(v0 - m) + __expf(v1 - m) +
              ((lane < NC - 64) ? __expf(v2 - m) : 0.f);
#pragma unroll
    for (int off = 16; off > 0; off >>= 1)
        s += __shfl_down_sync(0xffffffffu, s, off);

    unsigned mask = __ballot_sync(0xffffffffu, sbp[lane] == p);

    if (lane == 0) {
        float ov = __uint_as_float((unsigned)(og >> 32));
        int   idx = (int)(unsigned)og;
        if (mask) { idx = 31 - __clz(mask); ov = 2.0f; }

        int conf_t;
        if (ov < NEG_TH)      conf_t = 0;
        else if (ov < POS_TH) conf_t = -1;
        else                  conf_t = slab[idx] + 1;

        float lse = m + __logf(s);
        int ct = conf_t > 0 ? conf_t : 0;
        float nll = lse - row[ct];
        snv[warp] = (conf_t == 0) ? nll : 0.f;

        if (conf_t > 0) {
            atomicAdd(&g_loss_c, nll);
            atomicAdd(&g_npos[b], 1);
            atomicAdd(&g_total_pos, 1);
            float4 pr = ((const float4*)priors)[p];
            float4 gt = sgt[idx];
            float mcx = (gt.x + gt.z) * 0.5f;
            float mcy = (gt.y + gt.w) * 0.5f;
            float mw  = gt.z - gt.x;
            float mh  = gt.w - gt.y;
            float t0 = (mcx - pr.x) / (0.1f * pr.z);
            float t1 = (mcy - pr.y) / (0.1f * pr.w);
            float t2 = logf(mw / pr.z) / 0.2f;
            float t3 = logf(mh / pr.w) / 0.2f;
            float4 ld = ((const float4*)loc_data)[(size_t)b * PP + p];
            float acc = 0.f, d, ad;
            d = ld.x - t0; ad = fabsf(d); acc += (ad < 1.f) ? 0.5f * d * d : ad - 0.5f;
            d = ld.y - t1; ad = fabsf(d); acc += (ad < 1.f) ? 0.5f * d * d : ad - 0.5f;
            d = ld.z - t2; ad = fabsf(d); acc += (ad < 1.f) ? 0.5f * d * d : ad - 0.5f;
            d = ld.w - t3; ad = fabsf(d); acc += (ad < 1.f) ? 0.5f * d * d : ad - 0.5f;
            atomicAdd(&g_loss_l, acc);
        }
    }
    __syncthreads();
    if (threadIdx.x < NLLW)   // coalesced 64B negval write
        g_negval[(size_t)b * PP + blockIdx.x * NLLW + threadIdx.x] = snv[threadIdx.x];
}

// -------- Kernel 3: hard negative mining (R4 algorithm) + finalize + reset ---
extern __shared__ float sv[];  // PP floats

__device__ __forceinline__ int warp_suffix(int v, int lane) {
#pragma unroll
    for (int off = 1; off < 32; off <<= 1) {
        int t = __shfl_down_sync(0xffffffffu, v, off);
        if (lane + off < 32) v += t;
    }
    return v;
}

__device__ __forceinline__ void find_bin(int* hist, int nb, int Krem,
                                         int tid, int lane, int warpId,
                                         int* s_seg, int* psWstar,
                                         int* psB, int* psK) {
    int nsegs = nb >> 6;
    if (warpId < nsegs) {
        int base = warpId * 64;
        int s = hist[base + lane] + hist[base + 32 + lane];
        s = (int)__reduce_add_sync(0xffffffffu, (unsigned)s);
        if (lane == 0) s_seg[warpId] = s;
    }
    __syncthreads();
    if (tid < 32) {
        int v = (lane < nsegs) ? s_seg[lane] : 0;
        int ssum = warp_suffix(v, lane);
        unsigned bal = __ballot_sync(0xffffffffu, ssum >= Krem);
        int w = 31 - __clz(bal);
        int ssum_w = __shfl_sync(0xffffffffu, ssum, w);
        int v_w    = __shfl_sync(0xffffffffu, v, w);
        if (lane == 0) { *psWstar = w; *psK = Krem - (ssum_w - v_w); }
    }
    __syncthreads();
    if (warpId == *psWstar) {
        int base = warpId * 64;
        int K2 = *psK;
        int h1 = hist[base + 32 + lane];
        int s1 = warp_suffix(h1, lane);
        int tot1 = __shfl_sync(0xffffffffu, s1, 0);
        int bin, Kn;
        if (K2 <= tot1) {
            unsigned bal = __ballot_sync(0xffffffffu, s1 >= K2);
            int l = 31 - __clz(bal);
            bin = base + 32 + l;
            Kn = K2 - (__shfl_sync(0xffffffffu, s1, l) -
                       __shfl_sync(0xffffffffu, h1, l));
        } else {
            int K3 = K2 - tot1;
            int h0 = hist[base + lane];
            int s0 = warp_suffix(h0, lane);
            unsigned bal = __ballot_sync(0xffffffffu, s0 >= K3);
            int l = 31 - __clz(bal);
            bin = base + l;
            Kn = K3 - (__shfl_sync(0xffffffffu, s0, l) -
                       __shfl_sync(0xffffffffu, h0, l));
        }
        if (lane == 0) { *psB = bin; *psK = Kn; }
    }
    __syncthreads();
}

__global__ void __launch_bounds__(1024) mine_kernel(float* __restrict__ out) {
    const int b = blockIdx.x;
    const int tid = threadIdx.x;
    const int lane = tid & 31;
    const int warpId = tid >> 5;
    const int K = min(3 * g_npos[b], PP - 1);

    __shared__ int hist[2048];
    __shared__ int s_seg[32];
    __shared__ int sWstar, sB, sK;
    __shared__ int   s_cnt;
    __shared__ float s_sum;
    __shared__ int   s_last;

    if (K > 0) {
        const float* vals = g_negval + (size_t)b * PP;
        for (int p = tid; p < PP; p += 1024)
            sv[p] = vals[p];

        unsigned prefix = 0, himask = 0;
        int Krem = K;
        const int shifts[3]  = {20, 9, 0};
        const int nbins_a[3] = {2048, 2048, 512};

        for (int st = 0; st < 3; st++) {
            const int shift = shifts[st];
            const int nb = nbins_a[st];
            for (int i = tid; i < nb; i += 1024) hist[i] = 0;
            __syncthreads();
            for (int p = tid; p < PP; p += 1024) {
                unsigned u = __float_as_uint(sv[p]);
                if ((u & himask) == prefix)
                    atomicAdd(&hist[(u >> shift) & (nb - 1)], 1);
            }
            __syncthreads();
            find_bin(hist, nb, Krem, tid, lane, warpId, s_seg, &sWstar, &sB, &sK);
            prefix |= ((unsigned)sB) << shift;
            himask |= ((unsigned)(nb - 1)) << shift;
            Krem = sK;
            __syncthreads();
        }

        // sum of strictly-greater values + tie fill at threshold t
        if (tid == 0) { s_cnt = 0; s_sum = 0.f; }
        __syncthreads();
        float t = __uint_as_float(prefix);
        int cgt = 0;
        float sum = 0.f;
        for (int p = tid; p < PP; p += 1024) {
            float v = sv[p];
            if (__float_as_uint(v) > prefix) { cgt++; sum += v; }
        }
#pragma unroll
        for (int off = 16; off > 0; off >>= 1) {
            cgt += __shfl_down_sync(0xffffffffu, cgt, off);
            sum += __shfl_down_sync(0xffffffffu, sum, off);
        }
        if (lane == 0) { atomicAdd(&s_cnt, cgt); atomicAdd(&s_sum, sum); }
        __syncthreads();
        if (tid == 0)
            atomicAdd(&g_loss_c, s_sum + (float)(K - s_cnt) * t);
    }

    // ---- finalize: last block writes out and resets state for next replay ----
    __syncthreads();
    if (tid == 0) {
        __threadfence();
        s_last = (atomicAdd(&g_done, 1) == BB - 1) ? 1 : 0;
    }
    __syncthreads();
    if (s_last) {
        if (tid == 0) {
            float lc = atomicAdd(&g_loss_c, 0.f);
            float ll = atomicAdd(&g_loss_l, 0.f);
            int   tp = atomicAdd(&g_total_pos, 0);
            float N = (float)max(tp, 1);
            out[0] = ll / N;
            out[1] = lc / N;
            // reset scalars for the next graph replay
            g_loss_l = 0.f;
            g_loss_c = 0.f;
            g_total_pos = 0;
            g_done = 0;
        }
        if (tid < BB) g_npos[tid] = 0;
        if (tid < BB * NOBJ) g_bestkey[tid] = 0ull;
    }
}

extern "C" void kernel_launch(void* const* d_in, const int* in_sizes, int n_in,
                              void* d_out, int out_size) {
    const float* loc_data  = (const float*)d_in[0];
    const float* conf_data = (const float*)d_in[1];
    const float* priors    = (const float*)d_in[2];
    const float* gt_boxes  = (const float*)d_in[3];
    const int*   gt_labels = (const int*)d_in[4];
    float* out = (float*)d_out;

    cudaFuncSetAttribute(mine_kernel,
                         cudaFuncAttributeMaxDynamicSharedMemorySize,
                         PP * (int)sizeof(float));

    dim3 gridI((PP + 63) / 64, BB);
    iou_kernel<<<gridI, 256>>>(priors, gt_boxes);
    dim3 gridN(PP / NLLW, BB);
    nll_kernel<<<gridN, 512>>>(loc_data, conf_data, priors, gt_boxes, gt_labels);
    mine_kernel<<<BB, 1024, PP * (int)sizeof(float)>>>(out);
}

// round 8
// speedup vs baseline: 1.2588x; 1.2588x over previous
#include <cuda_runtime.h>
#include <cuda_bf16.h>
#include <math.h>

#define BB 16
#define PP 19248
#define NOBJ 32
#define NC 81
#define POS_TH 0.5f
#define NEG_TH 0.4f
#define FP 48     // priors per fused block (PP = 48 * 401)
#define FT 512    // threads per fused block
#define NV4 (FP * NC / 4)  // 972 float4s of conf per block

__device__ float              g_negval[BB * PP];
__device__ unsigned long long g_ovgt[BB * PP];     // (ov_bits << 32) | gt_idx
__device__ unsigned long long g_bestkey[BB * NOBJ];
__device__ float g_loss_l;
__device__ float g_loss_c;
__device__ int   g_npos[BB];
__device__ int   g_total_pos;
__device__ int   g_done;

// warp-collective LSE pieces over 81 values (row stride 1); all lanes get (m, s)
__device__ __forceinline__ void lse81(const float* __restrict__ row, int lane,
                                      float* pm, float* ps) {
    float v0 = row[lane];
    float v1 = row[lane + 32];
    float v2 = (lane < NC - 64) ? row[lane + 64] : -INFINITY;
    float m = fmaxf(fmaxf(v0, v1), v2);
#pragma unroll
    for (int off = 16; off > 0; off >>= 1)
        m = fmaxf(m, __shfl_xor_sync(0xffffffffu, m, off));
    float s = __expf(v0 - m) + __expf(v1 - m) +
              ((lane < NC - 64) ? __expf(v2 - m) : 0.f);
#pragma unroll
    for (int off = 16; off > 0; off >>= 1)
        s += __shfl_xor_sync(0xffffffffu, s, off);
    *pm = m;
    *ps = s;
}

// encode loc target (variances 0.1/0.2) and smooth-L1 vs loc prediction
__device__ __forceinline__ float enc_sl1(float4 pr, float4 gt, float4 ld) {
    float mcx = (gt.x + gt.z) * 0.5f;
    float mcy = (gt.y + gt.w) * 0.5f;
    float mw  = gt.z - gt.x;
    float mh  = gt.w - gt.y;
    float t0 = (mcx - pr.x) / (0.1f * pr.z);
    float t1 = (mcy - pr.y) / (0.1f * pr.w);
    float t2 = logf(mw / pr.z) / 0.2f;
    float t3 = logf(mh / pr.w) / 0.2f;
    float acc = 0.f, d, ad;
    d = ld.x - t0; ad = fabsf(d); acc += (ad < 1.f) ? 0.5f * d * d : ad - 0.5f;
    d = ld.y - t1; ad = fabsf(d); acc += (ad < 1.f) ? 0.5f * d * d : ad - 0.5f;
    d = ld.z - t2; ad = fabsf(d); acc += (ad < 1.f) ? 0.5f * d * d : ad - 0.5f;
    d = ld.w - t3; ad = fabsf(d); acc += (ad < 1.f) ? 0.5f * d * d : ad - 0.5f;
    return acc;
}

// ---- Kernel 1 (fused): IoU + provisional match + NLL + loc loss -------------
__global__ void __launch_bounds__(FT) fused_kernel(
        const float* __restrict__ loc_data,
        const float* __restrict__ conf_data,
        const float* __restrict__ priors,
        const float* __restrict__ gt_boxes,
        const int*   __restrict__ gt_labels) {
    const int b = blockIdx.y;
    const int p0 = blockIdx.x * FP;
    const int tid = threadIdx.x;
    const int warp = tid >> 5;
    const int lane = tid & 31;

    __shared__ float              sconf[FP * NC];
    __shared__ float4             sgt[NOBJ];
    __shared__ int                slab[NOBJ];
    __shared__ unsigned long long skey2[16][NOBJ];
    __shared__ float              snv[FP];
    __shared__ unsigned long long sovgt[FP];

    if (tid < NOBJ) {
        sgt[tid]  = ((const float4*)gt_boxes)[b * NOBJ + tid];
        slab[tid] = gt_labels[b * NOBJ + tid];
    }

    // issue conf loads early; IoU math below hides the DRAM latency
    const float4* src = (const float4*)(conf_data + ((size_t)b * PP + p0) * NC);
    float4 r0 = src[tid];
    float4 r1;
    const bool has1 = tid < (NV4 - FT);   // 460 threads carry a 2nd vector
    if (has1) r1 = src[tid + FT];

    __syncthreads();   // sgt/slab ready (does not wait on the loads above)

    // ---- IoU phase: this warp's 3 priors; lane n = gt n ----
    float4 g = sgt[lane];
    float area_g = (g.z - g.x) * (g.w - g.y);
    unsigned long long mykey = 0ull;
    unsigned myov[3];
    int      myidx[3];
    const int pbase = p0 + warp * 3;
#pragma unroll
    for (int j = 0; j < 3; j++) {
        int p = pbase + j;
        float4 pr = ((const float4*)priors)[p];
        float px1 = pr.x - pr.z * 0.5f, py1 = pr.y - pr.w * 0.5f;
        float px2 = pr.x + pr.z * 0.5f, py2 = pr.y + pr.w * 0.5f;
        float area_p = (px2 - px1) * (py2 - py1);
        float lx = fmaxf(g.x, px1), ly = fmaxf(g.y, py1);
        float rx = fminf(g.z, px2), ry = fminf(g.w, py2);
        float w = fmaxf(rx - lx, 0.f), h = fmaxf(ry - ly, 0.f);
        float inter = w * h;
        float ov = inter / (area_g + area_p - inter);  // IEEE div, matches ref

        unsigned long long key =
            ((unsigned long long)__float_as_uint(ov) << 32) |
            (unsigned long long)(0xFFFFFFFFu - (unsigned)p);
        mykey = (key > mykey) ? key : mykey;

        unsigned ovb = __float_as_uint(ov);           // ov >= 0: uint order ok
        unsigned umax = __reduce_max_sync(0xffffffffu, ovb);
        unsigned bal = __ballot_sync(0xffffffffu, ovb == umax);
        myov[j]  = umax;
        myidx[j] = __ffs(bal) - 1;                    // lowest gt on ties
    }
    skey2[warp][lane] = mykey;

    // ---- land staged conf in smem ----
    float4* sc4 = (float4*)sconf;
    sc4[tid] = r0;
    if (has1) sc4[tid + FT] = r1;
    __syncthreads();

    // warp 0 folds the 16 per-warp gt keys and publishes globally
    if (warp == 0) {
        unsigned long long k = skey2[0][lane];
#pragma unroll
        for (int w2 = 1; w2 < 16; w2++) {
            unsigned long long k2 = skey2[w2][lane];
            k = (k2 > k) ? k2 : k;
        }
        atomicMax(&g_bestkey[b * NOBJ + lane], k);
    }

    // ---- LSE + provisional loss per prior ----
#pragma unroll
    for (int j = 0; j < 3; j++) {
        int q = warp * 3 + j;
        int p = pbase + j;
        const float* row = sconf + q * NC;
        float m, s;
        lse81(row, lane, &m, &s);

        if (lane == 0) {
            float ov = __uint_as_float(myov[j]);
            int   idx = myidx[j];
            int conf_t;
            if (ov < NEG_TH)      conf_t = 0;
            else if (ov < POS_TH) conf_t = -1;
            else                  conf_t = slab[idx] + 1;

            float lse = m + __logf(s);
            int ct = conf_t > 0 ? conf_t : 0;
            float nll = lse - row[ct];
            snv[q]   = (conf_t == 0) ? nll : 0.f;
            sovgt[q] = ((unsigned long long)myov[j] << 32) |
                       (unsigned long long)(unsigned)idx;

            if (conf_t > 0) {
                atomicAdd(&g_loss_c, nll);
                atomicAdd(&g_npos[b], 1);
                atomicAdd(&g_total_pos, 1);
                float4 pr = ((const float4*)priors)[p];
                float4 ld = ((const float4*)loc_data)[(size_t)b * PP + p];
                atomicAdd(&g_loss_l, enc_sl1(pr, sgt[idx], ld));
            }
        }
    }
    __syncthreads();
    if (tid < FP) {   // coalesced final writes
        g_negval[(size_t)b * PP + p0 + tid] = snv[tid];
        g_ovgt[(size_t)b * PP + p0 + tid]   = sovgt[tid];
    }
}

// ---- Kernel 2 (fixup): apply forced matches for each gt's best prior --------
__global__ void __launch_bounds__(1024) fixup_kernel(
        const float* __restrict__ loc_data,
        const float* __restrict__ conf_data,
        const float* __restrict__ priors,
        const float* __restrict__ gt_boxes,
        const int*   __restrict__ gt_labels) {
    const int b = blockIdx.x;
    const int n = threadIdx.x >> 5;     // gt index, one warp each
    const int lane = threadIdx.x & 31;

    // lane i holds gt i's best prior for this batch
    unsigned q_lane = 0xFFFFFFFFu -
        (unsigned)(g_bestkey[b * NOBJ + lane] & 0xFFFFFFFFull);
    unsigned q_n = __shfl_sync(0xffffffffu, q_lane, n);
    unsigned mask = __ballot_sync(0xffffffffu, q_lane == q_n);
    if (31 - __clz(mask) != n) return;  // last-wins: only highest gt patches q

    const int q = (int)q_n;
    const float* row = conf_data + ((size_t)b * PP + q) * NC;
    float m, s;
    lse81(row, lane, &m, &s);

    if (lane == 0) {
        unsigned long long og = g_ovgt[(size_t)b * PP + q];
        float ov_old = __uint_as_float((unsigned)(og >> 32));
        int   idx_old = (int)(unsigned)(og & 0xFFFFFFFFull);

        float lse = m + __logf(s);
        int label_new = gt_labels[b * NOBJ + n];
        float nll_new = lse - row[label_new + 1];
        float4 pr = ((const float4*)priors)[q];
        float4 ld = ((const float4*)loc_data)[(size_t)b * PP + q];
        float4 gtn = ((const float4*)gt_boxes)[b * NOBJ + n];
        float sl1_new = enc_sl1(pr, gtn, ld);

        if (ov_old >= POS_TH) {
            // was provisionally positive with idx_old: swap contributions
            int label_old = gt_labels[b * NOBJ + idx_old];
            float nll_old = lse - row[label_old + 1];
            float4 gto = ((const float4*)gt_boxes)[b * NOBJ + idx_old];
            float sl1_old = enc_sl1(pr, gto, ld);
            atomicAdd(&g_loss_c, nll_new - nll_old);
            atomicAdd(&g_loss_l, sl1_new - sl1_old);
        } else {
            // was background or neutral: becomes positive
            atomicAdd(&g_loss_c, nll_new);
            atomicAdd(&g_loss_l, sl1_new);
            atomicAdd(&g_npos[b], 1);
            atomicAdd(&g_total_pos, 1);
            g_negval[(size_t)b * PP + q] = 0.f;
        }
    }
}

// ---- Kernel 3: hard negative mining (R4 algorithm) + finalize + reset -------
extern __shared__ float sv[];  // PP floats

__device__ __forceinline__ int warp_suffix(int v, int lane) {
#pragma unroll
    for (int off = 1; off < 32; off <<= 1) {
        int t = __shfl_down_sync(0xffffffffu, v, off);
        if (lane + off < 32) v += t;
    }
    return v;
}

__device__ __forceinline__ void find_bin(int* hist, int nb, int Krem,
                                         int tid, int lane, int warpId,
                                         int* s_seg, int* psWstar,
                                         int* psB, int* psK) {
    int nsegs = nb >> 6;
    if (warpId < nsegs) {
        int base = warpId * 64;
        int s = hist[base + lane] + hist[base + 32 + lane];
        s = (int)__reduce_add_sync(0xffffffffu, (unsigned)s);
        if (lane == 0) s_seg[warpId] = s;
    }
    __syncthreads();
    if (tid < 32) {
        int v = (lane < nsegs) ? s_seg[lane] : 0;
        int ssum = warp_suffix(v, lane);
        unsigned bal = __ballot_sync(0xffffffffu, ssum >= Krem);
        int w = 31 - __clz(bal);
        int ssum_w = __shfl_sync(0xffffffffu, ssum, w);
        int v_w    = __shfl_sync(0xffffffffu, v, w);
        if (lane == 0) { *psWstar = w; *psK = Krem - (ssum_w - v_w); }
    }
    __syncthreads();
    if (warpId == *psWstar) {
        int base = warpId * 64;
        int K2 = *psK;
        int h1 = hist[base + 32 + lane];
        int s1 = warp_suffix(h1, lane);
        int tot1 = __shfl_sync(0xffffffffu, s1, 0);
        int bin, Kn;
        if (K2 <= tot1) {
            unsigned bal = __ballot_sync(0xffffffffu, s1 >= K2);
            int l = 31 - __clz(bal);
            bin = base + 32 + l;
            Kn = K2 - (__shfl_sync(0xffffffffu, s1, l) -
                       __shfl_sync(0xffffffffu, h1, l));
        } else {
            int K3 = K2 - tot1;
            int h0 = hist[base + lane];
            int s0 = warp_suffix(h0, lane);
            unsigned bal = __ballot_sync(0xffffffffu, s0 >= K3);
            int l = 31 - __clz(bal);
            bin = base + l;
            Kn = K3 - (__shfl_sync(0xffffffffu, s0, l) -
                       __shfl_sync(0xffffffffu, h0, l));
        }
        if (lane == 0) { *psB = bin; *psK = Kn; }
    }
    __syncthreads();
}

__global__ void __launch_bounds__(1024) mine_kernel(float* __restrict__ out) {
    const int b = blockIdx.x;
    const int tid = threadIdx.x;
    const int lane = tid & 31;
    const int warpId = tid >> 5;
    const int K = min(3 * g_npos[b], PP - 1);

    __shared__ int hist[2048];
    __shared__ int s_seg[32];
    __shared__ int sWstar, sB, sK;
    __shared__ int   s_cnt;
    __shared__ float s_sum;
    __shared__ int   s_last;

    if (K > 0) {
        const float* vals = g_negval + (size_t)b * PP;
        for (int p = tid; p < PP; p += 1024)
            sv[p] = vals[p];

        unsigned prefix = 0, himask = 0;
        int Krem = K;
        const int shifts[3]  = {20, 9, 0};
        const int nbins_a[3] = {2048, 2048, 512};

        for (int st = 0; st < 3; st++) {
            const int shift = shifts[st];
            const int nb = nbins_a[st];
            for (int i = tid; i < nb; i += 1024) hist[i] = 0;
            __syncthreads();
            for (int p = tid; p < PP; p += 1024) {
                unsigned u = __float_as_uint(sv[p]);
                if ((u & himask) == prefix)
                    atomicAdd(&hist[(u >> shift) & (nb - 1)], 1);
            }
            __syncthreads();
            find_bin(hist, nb, Krem, tid, lane, warpId, s_seg, &sWstar, &sB, &sK);
            prefix |= ((unsigned)sB) << shift;
            himask |= ((unsigned)(nb - 1)) << shift;
            Krem = sK;
            __syncthreads();
        }

        if (tid == 0) { s_cnt = 0; s_sum = 0.f; }
        __syncthreads();
        float t = __uint_as_float(prefix);
        int cgt = 0;
        float sum = 0.f;
        for (int p = tid; p < PP; p += 1024) {
            float v = sv[p];
            if (__float_as_uint(v) > prefix) { cgt++; sum += v; }
        }
#pragma unroll
        for (int off = 16; off > 0; off >>= 1) {
            cgt += __shfl_down_sync(0xffffffffu, cgt, off);
            sum += __shfl_down_sync(0xffffffffu, sum, off);
        }
        if (lane == 0) { atomicAdd(&s_cnt, cgt); atomicAdd(&s_sum, sum); }
        __syncthreads();
        if (tid == 0)
            atomicAdd(&g_loss_c, s_sum + (float)(K - s_cnt) * t);
    }

    // finalize: last block writes out and resets state for next replay
    __syncthreads();
    if (tid == 0) {
        __threadfence();
        s_last = (atomicAdd(&g_done, 1) == BB - 1) ? 1 : 0;
    }
    __syncthreads();
    if (s_last) {
        if (tid == 0) {
            float lc = atomicAdd(&g_loss_c, 0.f);
            float ll = atomicAdd(&g_loss_l, 0.f);
            int   tp = atomicAdd(&g_total_pos, 0);
            float N = (float)max(tp, 1);
            out[0] = ll / N;
            out[1] = lc / N;
            g_loss_l = 0.f;
            g_loss_c = 0.f;
            g_total_pos = 0;
            g_done = 0;
        }
        if (tid < BB) g_npos[tid] = 0;
        if (tid < BB * NOBJ) g_bestkey[tid] = 0ull;
    }
}

extern "C" void kernel_launch(void* const* d_in, const int* in_sizes, int n_in,
                              void* d_out, int out_size) {
    const float* loc_data  = (const float*)d_in[0];
    const float* conf_data = (const float*)d_in[1];
    const float* priors    = (const float*)d_in[2];
    const float* gt_boxes  = (const float*)d_in[3];
    const int*   gt_labels = (const int*)d_in[4];
    float* out = (float*)d_out;

    cudaFuncSetAttribute(mine_kernel,
                         cudaFuncAttributeMaxDynamicSharedMemorySize,
                         PP * (int)sizeof(float));

    dim3 gridF(PP / FP, BB);
    fused_kernel<<<gridF, FT>>>(loc_data, conf_data, priors, gt_boxes, gt_labels);
    fixup_kernel<<<BB, 1024>>>(loc_data, conf_data, priors, gt_boxes, gt_labels);
    mine_kernel<<<BB, 1024, PP * (int)sizeof(float)>>>(out);
}

// round 9
// speedup vs baseline: 1.2597x; 1.0007x over previous
#include <cuda_runtime.h>
#include <cuda_bf16.h>
#include <math.h>

#define BB 16
#define PP 19248
#define NOBJ 32
#define NC 81
#define POS_TH 0.5f
#define NEG_TH 0.4f
#define FP 48     // priors per fused block (PP = 48 * 401)
#define FT 512    // threads per fused block
#define NV4 (FP * NC / 4)  // 972 float4s of conf per block

__device__ float              g_negval[BB * PP];
__device__ unsigned long long g_ovgt[BB * PP];     // (ov_bits << 32) | gt_idx
__device__ unsigned long long g_bestkey[BB * NOBJ];
__device__ float g_loss_l;
__device__ float g_loss_c;
__device__ int   g_npos[BB];
__device__ int   g_total_pos;
__device__ int   g_done;

// warp-collective LSE pieces over 81 values (row stride 1); all lanes get (m, s)
__device__ __forceinline__ void lse81(const float* __restrict__ row, int lane,
                                      float* pm, float* ps) {
    float v0 = row[lane];
    float v1 = row[lane + 32];
    float v2 = (lane < NC - 64) ? row[lane + 64] : -INFINITY;
    float m = fmaxf(fmaxf(v0, v1), v2);
#pragma unroll
    for (int off = 16; off > 0; off >>= 1)
        m = fmaxf(m, __shfl_xor_sync(0xffffffffu, m, off));
    float s = __expf(v0 - m) + __expf(v1 - m) +
              ((lane < NC - 64) ? __expf(v2 - m) : 0.f);
#pragma unroll
    for (int off = 16; off > 0; off >>= 1)
        s += __shfl_xor_sync(0xffffffffu, s, off);
    *pm = m;
    *ps = s;
}

// encode loc target (variances 0.1/0.2) and smooth-L1 vs loc prediction
__device__ __forceinline__ float enc_sl1(float4 pr, float4 gt, float4 ld) {
    float mcx = (gt.x + gt.z) * 0.5f;
    float mcy = (gt.y + gt.w) * 0.5f;
    float mw  = gt.z - gt.x;
    float mh  = gt.w - gt.y;
    float t0 = (mcx - pr.x) / (0.1f * pr.z);
    float t1 = (mcy - pr.y) / (0.1f * pr.w);
    float t2 = logf(mw / pr.z) / 0.2f;
    float t3 = logf(mh / pr.w) / 0.2f;
    float acc = 0.f, d, ad;
    d = ld.x - t0; ad = fabsf(d); acc += (ad < 1.f) ? 0.5f * d * d : ad - 0.5f;
    d = ld.y - t1; ad = fabsf(d); acc += (ad < 1.f) ? 0.5f * d * d : ad - 0.5f;
    d = ld.z - t2; ad = fabsf(d); acc += (ad < 1.f) ? 0.5f * d * d : ad - 0.5f;
    d = ld.w - t3; ad = fabsf(d); acc += (ad < 1.f) ? 0.5f * d * d : ad - 0.5f;
    return acc;
}

// ---- Kernel 1 (fused): IoU + provisional match + NLL + loc loss -------------
__global__ void __launch_bounds__(FT) fused_kernel(
        const float* __restrict__ loc_data,
        const float* __restrict__ conf_data,
        const float* __restrict__ priors,
        const float* __restrict__ gt_boxes,
        const int*   __restrict__ gt_labels) {
    const int b = blockIdx.y;
    const int p0 = blockIdx.x * FP;
    const int tid = threadIdx.x;
    const int warp = tid >> 5;
    const int lane = tid & 31;

    __shared__ float              sconf[FP * NC];
    __shared__ float4             sgt[NOBJ];
    __shared__ int                slab[NOBJ];
    __shared__ unsigned long long skey2[16][NOBJ];
    __shared__ float              snv[FP];
    __shared__ unsigned long long sovgt[FP];

    if (tid < NOBJ) {
        sgt[tid]  = ((const float4*)gt_boxes)[b * NOBJ + tid];
        slab[tid] = gt_labels[b * NOBJ + tid];
    }

    // issue conf loads early; IoU math below hides the DRAM latency
    const float4* src = (const float4*)(conf_data + ((size_t)b * PP + p0) * NC);
    float4 r0 = src[tid];
    float4 r1;
    const bool has1 = tid < (NV4 - FT);   // 460 threads carry a 2nd vector
    if (has1) r1 = src[tid + FT];

    __syncthreads();   // sgt/slab ready (does not wait on the loads above)

    // ---- IoU phase: this warp's 3 priors; lane n = gt n ----
    float4 g = sgt[lane];
    float area_g = (g.z - g.x) * (g.w - g.y);
    unsigned long long mykey = 0ull;
    unsigned myov[3];
    int      myidx[3];
    const int pbase = p0 + warp * 3;
#pragma unroll
    for (int j = 0; j < 3; j++) {
        int p = pbase + j;
        float4 pr = ((const float4*)priors)[p];
        float px1 = pr.x - pr.z * 0.5f, py1 = pr.y - pr.w * 0.5f;
        float px2 = pr.x + pr.z * 0.5f, py2 = pr.y + pr.w * 0.5f;
        float area_p = (px2 - px1) * (py2 - py1);
        float lx = fmaxf(g.x, px1), ly = fmaxf(g.y, py1);
        float rx = fminf(g.z, px2), ry = fminf(g.w, py2);
        float w = fmaxf(rx - lx, 0.f), h = fmaxf(ry - ly, 0.f);
        float inter = w * h;
        float ov = inter / (area_g + area_p - inter);  // IEEE div, matches ref

        unsigned long long key =
            ((unsigned long long)__float_as_uint(ov) << 32) |
            (unsigned long long)(0xFFFFFFFFu - (unsigned)p);
        mykey = (key > mykey) ? key : mykey;

        unsigned ovb = __float_as_uint(ov);           // ov >= 0: uint order ok
        unsigned umax = __reduce_max_sync(0xffffffffu, ovb);
        unsigned bal = __ballot_sync(0xffffffffu, ovb == umax);
        myov[j]  = umax;
        myidx[j] = __ffs(bal) - 1;                    // lowest gt on ties
    }
    skey2[warp][lane] = mykey;

    // ---- land staged conf in smem ----
    float4* sc4 = (float4*)sconf;
    sc4[tid] = r0;
    if (has1) sc4[tid + FT] = r1;
    __syncthreads();

    // warp 0 folds the 16 per-warp gt keys and publishes globally
    if (warp == 0) {
        unsigned long long k = skey2[0][lane];
#pragma unroll
        for (int w2 = 1; w2 < 16; w2++) {
            unsigned long long k2 = skey2[w2][lane];
            k = (k2 > k) ? k2 : k;
        }
        atomicMax(&g_bestkey[b * NOBJ + lane], k);
    }

    // ---- LSE + provisional loss per prior ----
#pragma unroll
    for (int j = 0; j < 3; j++) {
        int q = warp * 3 + j;
        int p = pbase + j;
        const float* row = sconf + q * NC;
        float m, s;
        lse81(row, lane, &m, &s);

        if (lane == 0) {
            float ov = __uint_as_float(myov[j]);
            int   idx = myidx[j];
            int conf_t;
            if (ov < NEG_TH)      conf_t = 0;
            else if (ov < POS_TH) conf_t = -1;
            else                  conf_t = slab[idx] + 1;

            float lse = m + __logf(s);
            int ct = conf_t > 0 ? conf_t : 0;
            float nll = lse - row[ct];
            snv[q]   = (conf_t == 0) ? nll : 0.f;
            sovgt[q] = ((unsigned long long)myov[j] << 32) |
                       (unsigned long long)(unsigned)idx;

            if (conf_t > 0) {
                atomicAdd(&g_loss_c, nll);
                atomicAdd(&g_npos[b], 1);
                atomicAdd(&g_total_pos, 1);
                float4 pr = ((const float4*)priors)[p];
                float4 ld = ((const float4*)loc_data)[(size_t)b * PP + p];
                atomicAdd(&g_loss_l, enc_sl1(pr, sgt[idx], ld));
            }
        }
    }
    __syncthreads();
    if (tid < FP) {   // coalesced final writes
        g_negval[(size_t)b * PP + p0 + tid] = snv[tid];
        g_ovgt[(size_t)b * PP + p0 + tid]   = sovgt[tid];
    }
}

// ---- Kernel 2 (fixup): apply forced matches for each gt's best prior --------
__global__ void __launch_bounds__(1024) fixup_kernel(
        const float* __restrict__ loc_data,
        const float* __restrict__ conf_data,
        const float* __restrict__ priors,
        const float* __restrict__ gt_boxes,
        const int*   __restrict__ gt_labels) {
    const int b = blockIdx.x;
    const int n = threadIdx.x >> 5;     // gt index, one warp each
    const int lane = threadIdx.x & 31;

    // lane i holds gt i's best prior for this batch
    unsigned q_lane = 0xFFFFFFFFu -
        (unsigned)(g_bestkey[b * NOBJ + lane] & 0xFFFFFFFFull);
    unsigned q_n = __shfl_sync(0xffffffffu, q_lane, n);
    unsigned mask = __ballot_sync(0xffffffffu, q_lane == q_n);
    if (31 - __clz(mask) != n) return;  // last-wins: only highest gt patches q

    const int q = (int)q_n;
    const float* row = conf_data + ((size_t)b * PP + q) * NC;
    float m, s;
    lse81(row, lane, &m, &s);

    if (lane == 0) {
        unsigned long long og = g_ovgt[(size_t)b * PP + q];
        float ov_old = __uint_as_float((unsigned)(og >> 32));
        int   idx_old = (int)(unsigned)(og & 0xFFFFFFFFull);

        float lse = m + __logf(s);
        int label_new = gt_labels[b * NOBJ + n];
        float nll_new = lse - row[label_new + 1];
        float4 pr = ((const float4*)priors)[q];
        float4 ld = ((const float4*)loc_data)[(size_t)b * PP + q];
        float4 gtn = ((const float4*)gt_boxes)[b * NOBJ + n];
        float sl1_new = enc_sl1(pr, gtn, ld);

        if (ov_old >= POS_TH) {
            // was provisionally positive with idx_old: swap contributions
            int label_old = gt_labels[b * NOBJ + idx_old];
            float nll_old = lse - row[label_old + 1];
            float4 gto = ((const float4*)gt_boxes)[b * NOBJ + idx_old];
            float sl1_old = enc_sl1(pr, gto, ld);
            atomicAdd(&g_loss_c, nll_new - nll_old);
            atomicAdd(&g_loss_l, sl1_new - sl1_old);
        } else {
            // was background or neutral: becomes positive
            atomicAdd(&g_loss_c, nll_new);
            atomicAdd(&g_loss_l, sl1_new);
            atomicAdd(&g_npos[b], 1);
            atomicAdd(&g_total_pos, 1);
            g_negval[(size_t)b * PP + q] = 0.f;
        }
    }
}

// ---- Kernel 3: hard negative mining (R4 algorithm) + finalize + reset -------
extern __shared__ float sv[];  // PP floats

__device__ __forceinline__ int warp_suffix(int v, int lane) {
#pragma unroll
    for (int off = 1; off < 32; off <<= 1) {
        int t = __shfl_down_sync(0xffffffffu, v, off);
        if (lane + off < 32) v += t;
    }
    return v;
}

__device__ __forceinline__ void find_bin(int* hist, int nb, int Krem,
                                         int tid, int lane, int warpId,
                                         int* s_seg, int* psWstar,
                                         int* psB, int* psK) {
    int nsegs = nb >> 6;
    if (warpId < nsegs) {
        int base = warpId * 64;
        int s = hist[base + lane] + hist[base + 32 + lane];
        s = (int)__reduce_add_sync(0xffffffffu, (unsigned)s);
        if (lane == 0) s_seg[warpId] = s;
    }
    __syncthreads();
    if (tid < 32) {
        int v = (lane < nsegs) ? s_seg[lane] : 0;
        int ssum = warp_suffix(v, lane);
        unsigned bal = __ballot_sync(0xffffffffu, ssum >= Krem);
        int w = 31 - __clz(bal);
        int ssum_w = __shfl_sync(0xffffffffu, ssum, w);
        int v_w    = __shfl_sync(0xffffffffu, v, w);
        if (lane == 0) { *psWstar = w; *psK = Krem - (ssum_w - v_w); }
    }
    __syncthreads();
    if (warpId == *psWstar) {
        int base = warpId * 64;
        int K2 = *psK;
        int h1 = hist[base + 32 + lane];
        int s1 = warp_suffix(h1, lane);
        int tot1 = __shfl_sync(0xffffffffu, s1, 0);
        int bin, Kn;
        if (K2 <= tot1) {
            unsigned bal = __ballot_sync(0xffffffffu, s1 >= K2);
            int l = 31 - __clz(bal);
            bin = base + 32 + l;
            Kn = K2 - (__shfl_sync(0xffffffffu, s1, l) -
                       __shfl_sync(0xffffffffu, h1, l));
        } else {
            int K3 = K2 - tot1;
            int h0 = hist[base + lane];
            int s0 = warp_suffix(h0, lane);
            unsigned bal = __ballot_sync(0xffffffffu, s0 >= K3);
            int l = 31 - __clz(bal);
            bin = base + l;
            Kn = K3 - (__shfl_sync(0xffffffffu, s0, l) -
                       __shfl_sync(0xffffffffu, h0, l));
        }
        if (lane == 0) { *psB = bin; *psK = Kn; }
    }
    __syncthreads();
}

__global__ void __launch_bounds__(1024) mine_kernel(float* __restrict__ out) {
    const int b = blockIdx.x;
    const int tid = threadIdx.x;
    const int lane = tid & 31;
    const int warpId = tid >> 5;
    const int K = min(3 * g_npos[b], PP - 1);

    __shared__ int hist[2048];
    __shared__ int s_seg[32];
    __shared__ int sWstar, sB, sK;
    __shared__ int   s_cnt;
    __shared__ float s_sum;
    __shared__ int   s_last;

    if (K > 0) {
        const float* vals = g_negval + (size_t)b * PP;
        for (int p = tid; p < PP; p += 1024)
            sv[p] = vals[p];

        unsigned prefix = 0, himask = 0;
        int Krem = K;
        const int shifts[3]  = {20, 9, 0};
        const int nbins_a[3] = {2048, 2048, 512};

        for (int st = 0; st < 3; st++) {
            const int shift = shifts[st];
            const int nb = nbins_a[st];
            for (int i = tid; i < nb; i += 1024) hist[i] = 0;
            __syncthreads();
            for (int p = tid; p < PP; p += 1024) {
                unsigned u = __float_as_uint(sv[p]);
                if ((u & himask) == prefix)
                    atomicAdd(&hist[(u >> shift) & (nb - 1)], 1);
            }
            __syncthreads();
            find_bin(hist, nb, Krem, tid, lane, warpId, s_seg, &sWstar, &sB, &sK);
            prefix |= ((unsigned)sB) << shift;
            himask |= ((unsigned)(nb - 1)) << shift;
            Krem = sK;
            __syncthreads();
        }

        if (tid == 0) { s_cnt = 0; s_sum = 0.f; }
        __syncthreads();
        float t = __uint_as_float(prefix);
        int cgt = 0;
        float sum = 0.f;
        for (int p = tid; p < PP; p += 1024) {
            float v = sv[p];
            if (__float_as_uint(v) > prefix) { cgt++; sum += v; }
        }
#pragma unroll
        for (int off = 16; off > 0; off >>= 1) {
            cgt += __shfl_down_sync(0xffffffffu, cgt, off);
            sum += __shfl_down_sync(0xffffffffu, sum, off);
        }
        if (lane == 0) { atomicAdd(&s_cnt, cgt); atomicAdd(&s_sum, sum); }
        __syncthreads();
        if (tid == 0)
            atomicAdd(&g_loss_c, s_sum + (float)(K - s_cnt) * t);
    }

    // finalize: last block writes out and resets state for next replay
    __syncthreads();
    if (tid == 0) {
        __threadfence();
        s_last = (atomicAdd(&g_done, 1) == BB - 1) ? 1 : 0;
    }
    __syncthreads();
    if (s_last) {
        if (tid == 0) {
            float lc = atomicAdd(&g_loss_c, 0.f);
            float ll = atomicAdd(&g_loss_l, 0.f);
            int   tp = atomicAdd(&g_total_pos, 0);
            float N = (float)max(tp, 1);
            out[0] = ll / N;
            out[1] = lc / N;
            g_loss_l = 0.f;
            g_loss_c = 0.f;
            g_total_pos = 0;
            g_done = 0;
        }
        if (tid < BB) g_npos[tid] = 0;
        if (tid < BB * NOBJ) g_bestkey[tid] = 0ull;
    }
}

extern "C" void kernel_launch(void* const* d_in, const int* in_sizes, int n_in,
                              void* d_out, int out_size) {
    const float* loc_data  = (const float*)d_in[0];
    const float* conf_data = (const float*)d_in[1];
    const float* priors    = (const float*)d_in[2];
    const float* gt_boxes  = (const float*)d_in[3];
    const int*   gt_labels = (const int*)d_in[4];
    float* out = (float*)d_out;

    cudaFuncSetAttribute(mine_kernel,
                         cudaFuncAttributeMaxDynamicSharedMemorySize,
                         PP * (int)sizeof(float));

    dim3 gridF(PP / FP, BB);
    fused_kernel<<<gridF, FT>>>(loc_data, conf_data, priors, gt_boxes, gt_labels);
    fixup_kernel<<<BB, 1024>>>(loc_data, conf_data, priors, gt_boxes, gt_labels);
    mine_kernel<<<BB, 1024, PP * (int)sizeof(float)>>>(out);
}

// round 10
// speedup vs baseline: 1.2634x; 1.0029x over previous
#include <cuda_runtime.h>
#include <cuda_bf16.h>
#include <math.h>

#define BB 16
#define PP 19248
#define NOBJ 32
#define NC 81
#define POS_TH 0.5f
#define NEG_TH 0.4f
#define FP 48     // priors per fused block (PP = 48 * 401)
#define FT 512    // threads per fused block
#define NV4 (FP * NC / 4)  // 972 float4s of conf per block

__device__ float              g_negval[BB * PP];
__device__ unsigned long long g_ovgt[BB * PP];     // (ov_bits << 32) | gt_idx
__device__ unsigned long long g_bestkey[BB * NOBJ];
__device__ float g_loss_l;
__device__ float g_loss_c;
__device__ int   g_npos[BB];
__device__ int   g_total_pos;
__device__ int   g_done;

// warp-collective LSE pieces over 81 values (row stride 1); all lanes get (m, s)
__device__ __forceinline__ void lse81(const float* __restrict__ row, int lane,
                                      float* pm, float* ps) {
    float v0 = row[lane];
    float v1 = row[lane + 32];
    float v2 = (lane < NC - 64) ? row[lane + 64] : -INFINITY;
    float m = fmaxf(fmaxf(v0, v1), v2);
#pragma unroll
    for (int off = 16; off > 0; off >>= 1)
        m = fmaxf(m, __shfl_xor_sync(0xffffffffu, m, off));
    float s = __expf(v0 - m) + __expf(v1 - m) +
              ((lane < NC - 64) ? __expf(v2 - m) : 0.f);
#pragma unroll
    for (int off = 16; off > 0; off >>= 1)
        s += __shfl_xor_sync(0xffffffffu, s, off);
    *pm = m;
    *ps = s;
}

// encode loc target (variances 0.1/0.2) and smooth-L1 vs loc prediction
__device__ __forceinline__ float enc_sl1(float4 pr, float4 gt, float4 ld) {
    float mcx = (gt.x + gt.z) * 0.5f;
    float mcy = (gt.y + gt.w) * 0.5f;
    float mw  = gt.z - gt.x;
    float mh  = gt.w - gt.y;
    float t0 = (mcx - pr.x) / (0.1f * pr.z);
    float t1 = (mcy - pr.y) / (0.1f * pr.w);
    float t2 = logf(mw / pr.z) / 0.2f;
    float t3 = logf(mh / pr.w) / 0.2f;
    float acc = 0.f, d, ad;
    d = ld.x - t0; ad = fabsf(d); acc += (ad < 1.f) ? 0.5f * d * d : ad - 0.5f;
    d = ld.y - t1; ad = fabsf(d); acc += (ad < 1.f) ? 0.5f * d * d : ad - 0.5f;
    d = ld.z - t2; ad = fabsf(d); acc += (ad < 1.f) ? 0.5f * d * d : ad - 0.5f;
    d = ld.w - t3; ad = fabsf(d); acc += (ad < 1.f) ? 0.5f * d * d : ad - 0.5f;
    return acc;
}

// ---- Kernel 1 (fused): IoU + provisional match + NLL + loc loss -------------
__global__ void __launch_bounds__(FT) fused_kernel(
        const float* __restrict__ loc_data,
        const float* __restrict__ conf_data,
        const float* __restrict__ priors,
        const float* __restrict__ gt_boxes,
        const int*   __restrict__ gt_labels) {
    const int b = blockIdx.y;
    const int p0 = blockIdx.x * FP;
    const int tid = threadIdx.x;
    const int warp = tid >> 5;
    const int lane = tid & 31;

    __shared__ float              sconf[FP * NC];
    __shared__ float4             sgt[NOBJ];
    __shared__ int                slab[NOBJ];
    __shared__ unsigned long long skey2[16][NOBJ];
    __shared__ float              snv[FP];
    __shared__ unsigned long long sovgt[FP];

    if (tid < NOBJ) {
        sgt[tid]  = ((const float4*)gt_boxes)[b * NOBJ + tid];
        slab[tid] = gt_labels[b * NOBJ + tid];
    }

    // issue conf loads early; IoU math below hides the DRAM latency
    const float4* src = (const float4*)(conf_data + ((size_t)b * PP + p0) * NC);
    float4 r0 = src[tid];
    float4 r1;
    const bool has1 = tid < (NV4 - FT);   // 460 threads carry a 2nd vector
    if (has1) r1 = src[tid + FT];

    __syncthreads();   // sgt/slab ready (does not wait on the loads above)

    // ---- IoU phase: this warp's 3 priors; lane n = gt n ----
    float4 g = sgt[lane];
    float area_g = (g.z - g.x) * (g.w - g.y);
    unsigned long long mykey = 0ull;
    unsigned myov[3];
    int      myidx[3];
    const int pbase = p0 + warp * 3;
#pragma unroll
    for (int j = 0; j < 3; j++) {
        int p = pbase + j;
        float4 pr = ((const float4*)priors)[p];
        float px1 = pr.x - pr.z * 0.5f, py1 = pr.y - pr.w * 0.5f;
        float px2 = pr.x + pr.z * 0.5f, py2 = pr.y + pr.w * 0.5f;
        float area_p = (px2 - px1) * (py2 - py1);
        float lx = fmaxf(g.x, px1), ly = fmaxf(g.y, py1);
        float rx = fminf(g.z, px2), ry = fminf(g.w, py2);
        float w = fmaxf(rx - lx, 0.f), h = fmaxf(ry - ly, 0.f);
        float inter = w * h;
        float ov = inter / (area_g + area_p - inter);  // IEEE div, matches ref

        unsigned long long key =
            ((unsigned long long)__float_as_uint(ov) << 32) |
            (unsigned long long)(0xFFFFFFFFu - (unsigned)p);
        mykey = (key > mykey) ? key : mykey;

        unsigned ovb = __float_as_uint(ov);           // ov >= 0: uint order ok
        unsigned umax = __reduce_max_sync(0xffffffffu, ovb);
        unsigned bal = __ballot_sync(0xffffffffu, ovb == umax);
        myov[j]  = umax;
        myidx[j] = __ffs(bal) - 1;                    // lowest gt on ties
    }
    skey2[warp][lane] = mykey;

    // ---- land staged conf in smem ----
    float4* sc4 = (float4*)sconf;
    sc4[tid] = r0;
    if (has1) sc4[tid + FT] = r1;
    __syncthreads();

    // warp 0 folds the 16 per-warp gt keys and publishes globally
    if (warp == 0) {
        unsigned long long k = skey2[0][lane];
#pragma unroll
        for (int w2 = 1; w2 < 16; w2++) {
            unsigned long long k2 = skey2[w2][lane];
            k = (k2 > k) ? k2 : k;
        }
        atomicMax(&g_bestkey[b * NOBJ + lane], k);
    }

    // ---- LSE + provisional loss per prior ----
#pragma unroll
    for (int j = 0; j < 3; j++) {
        int q = warp * 3 + j;
        int p = pbase + j;
        const float* row = sconf + q * NC;
        float m, s;
        lse81(row, lane, &m, &s);

        if (lane == 0) {
            float ov = __uint_as_float(myov[j]);
            int   idx = myidx[j];
            int conf_t;
            if (ov < NEG_TH)      conf_t = 0;
            else if (ov < POS_TH) conf_t = -1;
            else                  conf_t = slab[idx] + 1;

            float lse = m + __logf(s);
            int ct = conf_t > 0 ? conf_t : 0;
            float nll = lse - row[ct];
            snv[q]   = (conf_t == 0) ? nll : 0.f;
            sovgt[q] = ((unsigned long long)myov[j] << 32) |
                       (unsigned long long)(unsigned)idx;

            if (conf_t > 0) {
                atomicAdd(&g_loss_c, nll);
                atomicAdd(&g_npos[b], 1);
                atomicAdd(&g_total_pos, 1);
                float4 pr = ((const float4*)priors)[p];
                float4 ld = ((const float4*)loc_data)[(size_t)b * PP + p];
                atomicAdd(&g_loss_l, enc_sl1(pr, sgt[idx], ld));
            }
        }
    }
    __syncthreads();
    if (tid < FP) {   // coalesced final writes
        g_negval[(size_t)b * PP + p0 + tid] = snv[tid];
        g_ovgt[(size_t)b * PP + p0 + tid]   = sovgt[tid];
    }
}

// ---- Kernel 2 (fixup): apply forced matches for each gt's best prior --------
__global__ void __launch_bounds__(1024) fixup_kernel(
        const float* __restrict__ loc_data,
        const float* __restrict__ conf_data,
        const float* __restrict__ priors,
        const float* __restrict__ gt_boxes,
        const int*   __restrict__ gt_labels) {
    const int b = blockIdx.x;
    const int n = threadIdx.x >> 5;     // gt index, one warp each
    const int lane = threadIdx.x & 31;

    // lane i holds gt i's best prior for this batch
    unsigned q_lane = 0xFFFFFFFFu -
        (unsigned)(g_bestkey[b * NOBJ + lane] & 0xFFFFFFFFull);
    unsigned q_n = __shfl_sync(0xffffffffu, q_lane, n);
    unsigned mask = __ballot_sync(0xffffffffu, q_lane == q_n);
    if (31 - __clz(mask) != n) return;  // last-wins: only highest gt patches q

    const int q = (int)q_n;
    const float* row = conf_data + ((size_t)b * PP + q) * NC;
    float m, s;
    lse81(row, lane, &m, &s);

    if (lane == 0) {
        unsigned long long og = g_ovgt[(size_t)b * PP + q];
        float ov_old = __uint_as_float((unsigned)(og >> 32));
        int   idx_old = (int)(unsigned)(og & 0xFFFFFFFFull);

        float lse = m + __logf(s);
        int label_new = gt_labels[b * NOBJ + n];
        float nll_new = lse - row[label_new + 1];
        float4 pr = ((const float4*)priors)[q];
        float4 ld = ((const float4*)loc_data)[(size_t)b * PP + q];
        float4 gtn = ((const float4*)gt_boxes)[b * NOBJ + n];
        float sl1_new = enc_sl1(pr, gtn, ld);

        if (ov_old >= POS_TH) {
            // was provisionally positive with idx_old: swap contributions
            int label_old = gt_labels[b * NOBJ + idx_old];
            float nll_old = lse - row[label_old + 1];
            float4 gto = ((const float4*)gt_boxes)[b * NOBJ + idx_old];
            float sl1_old = enc_sl1(pr, gto, ld);
            atomicAdd(&g_loss_c, nll_new - nll_old);
            atomicAdd(&g_loss_l, sl1_new - sl1_old);
        } else {
            // was background or neutral: becomes positive
            atomicAdd(&g_loss_c, nll_new);
            atomicAdd(&g_loss_l, sl1_new);
            atomicAdd(&g_npos[b], 1);
            atomicAdd(&g_total_pos, 1);
            g_negval[(size_t)b * PP + q] = 0.f;
        }
    }
}

// ---- Kernel 3: hard negative mining (R4 algorithm) + finalize + reset -------
extern __shared__ float sv[];  // PP floats

__device__ __forceinline__ int warp_suffix(int v, int lane) {
#pragma unroll
    for (int off = 1; off < 32; off <<= 1) {
        int t = __shfl_down_sync(0xffffffffu, v, off);
        if (lane + off < 32) v += t;
    }
    return v;
}

__device__ __forceinline__ void find_bin(int* hist, int nb, int Krem,
                                         int tid, int lane, int warpId,
                                         int* s_seg, int* psWstar,
                                         int* psB, int* psK) {
    int nsegs = nb >> 6;
    if (warpId < nsegs) {
        int base = warpId * 64;
        int s = hist[base + lane] + hist[base + 32 + lane];
        s = (int)__reduce_add_sync(0xffffffffu, (unsigned)s);
        if (lane == 0) s_seg[warpId] = s;
    }
    __syncthreads();
    if (tid < 32) {
        int v = (lane < nsegs) ? s_seg[lane] : 0;
        int ssum = warp_suffix(v, lane);
        unsigned bal = __ballot_sync(0xffffffffu, ssum >= Krem);
        int w = 31 - __clz(bal);
        int ssum_w = __shfl_sync(0xffffffffu, ssum, w);
        int v_w    = __shfl_sync(0xffffffffu, v, w);
        if (lane == 0) { *psWstar = w; *psK = Krem - (ssum_w - v_w); }
    }
    __syncthreads();
    if (warpId == *psWstar) {
        int base = warpId * 64;
        int K2 = *psK;
        int h1 = hist[base + 32 + lane];
        int s1 = warp_suffix(h1, lane);
        int tot1 = __shfl_sync(0xffffffffu, s1, 0);
        int bin, Kn;
        if (K2 <= tot1) {
            unsigned bal = __ballot_sync(0xffffffffu, s1 >= K2);
            int l = 31 - __clz(bal);
            bin = base + 32 + l;
            Kn = K2 - (__shfl_sync(0xffffffffu, s1, l) -
                       __shfl_sync(0xffffffffu, h1, l));
        } else {
            int K3 = K2 - tot1;
            int h0 = hist[base + lane];
            int s0 = warp_suffix(h0, lane);
            unsigned bal = __ballot_sync(0xffffffffu, s0 >= K3);
            int l = 31 - __clz(bal);
            bin = base + l;
            Kn = K3 - (__shfl_sync(0xffffffffu, s0, l) -
                       __shfl_sync(0xffffffffu, h0, l));
        }
        if (lane == 0) { *psB = bin; *psK = Kn; }
    }
    __syncthreads();
}

__global__ void __launch_bounds__(1024) mine_kernel(float* __restrict__ out) {
    const int b = blockIdx.x;
    const int tid = threadIdx.x;
    const int lane = tid & 31;
    const int warpId = tid >> 5;
    const int K = min(3 * g_npos[b], PP - 1);

    __shared__ int hist[2048];
    __shared__ int s_seg[32];
    __shared__ int sWstar, sB, sK;
    __shared__ int   s_cnt;
    __shared__ float s_sum;
    __shared__ int   s_last;

    if (K > 0) {
        const float* vals = g_negval + (size_t)b * PP;
        for (int p = tid; p < PP; p += 1024)
            sv[p] = vals[p];

        unsigned prefix = 0, himask = 0;
        int Krem = K;
        const int shifts[3]  = {20, 9, 0};
        const int nbins_a[3] = {2048, 2048, 512};

        for (int st = 0; st < 3; st++) {
            const int shift = shifts[st];
            const int nb = nbins_a[st];
            for (int i = tid; i < nb; i += 1024) hist[i] = 0;
            __syncthreads();
            for (int p = tid; p < PP; p += 1024) {
                unsigned u = __float_as_uint(sv[p]);
                if ((u & himask) == prefix)
                    atomicAdd(&hist[(u >> shift) & (nb - 1)], 1);
            }
            __syncthreads();
            find_bin(hist, nb, Krem, tid, lane, warpId, s_seg, &sWstar, &sB, &sK);
            prefix |= ((unsigned)sB) << shift;
            himask |= ((unsigned)(nb - 1)) << shift;
            Krem = sK;
            __syncthreads();
        }

        if (tid == 0) { s_cnt = 0; s_sum = 0.f; }
        __syncthreads();
        float t = __uint_as_float(prefix);
        int cgt = 0;
        float sum = 0.f;
        for (int p = tid; p < PP; p += 1024) {
            float v = sv[p];
            if (__float_as_uint(v) > prefix) { cgt++; sum += v; }
        }
#pragma unroll
        for (int off = 16; off > 0; off >>= 1) {
            cgt += __shfl_down_sync(0xffffffffu, cgt, off);
            sum += __shfl_down_sync(0xffffffffu, sum, off);
        }
        if (lane == 0) { atomicAdd(&s_cnt, cgt); atomicAdd(&s_sum, sum); }
        __syncthreads();
        if (tid == 0)
            atomicAdd(&g_loss_c, s_sum + (float)(K - s_cnt) * t);
    }

    // finalize: last block writes out and resets state for next replay
    __syncthreads();
    if (tid == 0) {
        __threadfence();
        s_last = (atomicAdd(&g_done, 1) == BB - 1) ? 1 : 0;
    }
    __syncthreads();
    if (s_last) {
        if (tid == 0) {
            float lc = atomicAdd(&g_loss_c, 0.f);
            float ll = atomicAdd(&g_loss_l, 0.f);
            int   tp = atomicAdd(&g_total_pos, 0);
            float N = (float)max(tp, 1);
            out[0] = ll / N;
            out[1] = lc / N;
            g_loss_l = 0.f;
            g_loss_c = 0.f;
            g_total_pos = 0;
            g_done = 0;
        }
        if (tid < BB) g_npos[tid] = 0;
        if (tid < BB * NOBJ) g_bestkey[tid] = 0ull;
    }
}

extern "C" void kernel_launch(void* const* d_in, const int* in_sizes, int n_in,
                              void* d_out, int out_size) {
    const float* loc_data  = (const float*)d_in[0];
    const float* conf_data = (const float*)d_in[1];
    const float* priors    = (const float*)d_in[2];
    const float* gt_boxes  = (const float*)d_in[3];
    const int*   gt_labels = (const int*)d_in[4];
    float* out = (float*)d_out;

    cudaFuncSetAttribute(mine_kernel,
                         cudaFuncAttributeMaxDynamicSharedMemorySize,
                         PP * (int)sizeof(float));

    dim3 gridF(PP / FP, BB);
    fused_kernel<<<gridF, FT>>>(loc_data, conf_data, priors, gt_boxes, gt_labels);
    fixup_kernel<<<BB, 1024>>>(loc_data, conf_data, priors, gt_boxes, gt_labels);
    mine_kernel<<<BB, 1024, PP * (int)sizeof(float)>>>(out);
}

// round 11
// speedup vs baseline: 1.2684x; 1.0040x over previous
#include <cuda_runtime.h>
#include <cuda_bf16.h>
#include <math.h>

#define BB 16
#define PP 19248
#define NOBJ 32
#define NC 81
#define POS_TH 0.5f
#define NEG_TH 0.4f
#define FP 48     // priors per fused block (PP = 48 * 401)
#define FT 512    // threads per fused block
#define NV4 (FP * NC / 4)  // 972 float4s of conf per block

__device__ float              g_negval[BB * PP];
__device__ unsigned long long g_ovgt[BB * PP];     // (ov_bits << 32) | gt_idx
__device__ unsigned long long g_bestkey[BB * NOBJ];
__device__ float g_loss_l;
__device__ float g_loss_c;
__device__ int   g_npos[BB];
__device__ int   g_total_pos;
__device__ int   g_done;

// warp-collective LSE pieces over 81 values (row stride 1); all lanes get (m, s)
__device__ __forceinline__ void lse81(const float* __restrict__ row, int lane,
                                      float* pm, float* ps) {
    float v0 = row[lane];
    float v1 = row[lane + 32];
    float v2 = (lane < NC - 64) ? row[lane + 64] : -INFINITY;
    float m = fmaxf(fmaxf(v0, v1), v2);
#pragma unroll
    for (int off = 16; off > 0; off >>= 1)
        m = fmaxf(m, __shfl_xor_sync(0xffffffffu, m, off));
    float s = __expf(v0 - m) + __expf(v1 - m) +
              ((lane < NC - 64) ? __expf(v2 - m) : 0.f);
#pragma unroll
    for (int off = 16; off > 0; off >>= 1)
        s += __shfl_xor_sync(0xffffffffu, s, off);
    *pm = m;
    *ps = s;
}

// encode loc target (variances 0.1/0.2) and smooth-L1 vs loc prediction
__device__ __forceinline__ float enc_sl1(float4 pr, float4 gt, float4 ld) {
    float mcx = (gt.x + gt.z) * 0.5f;
    float mcy = (gt.y + gt.w) * 0.5f;
    float mw  = gt.z - gt.x;
    float mh  = gt.w - gt.y;
    float t0 = (mcx - pr.x) / (0.1f * pr.z);
    float t1 = (mcy - pr.y) / (0.1f * pr.w);
    float t2 = logf(mw / pr.z) / 0.2f;
    float t3 = logf(mh / pr.w) / 0.2f;
    float acc = 0.f, d, ad;
    d = ld.x - t0; ad = fabsf(d); acc += (ad < 1.f) ? 0.5f * d * d : ad - 0.5f;
    d = ld.y - t1; ad = fabsf(d); acc += (ad < 1.f) ? 0.5f * d * d : ad - 0.5f;
    d = ld.z - t2; ad = fabsf(d); acc += (ad < 1.f) ? 0.5f * d * d : ad - 0.5f;
    d = ld.w - t3; ad = fabsf(d); acc += (ad < 1.f) ? 0.5f * d * d : ad - 0.5f;
    return acc;
}

// ---- Kernel 1 (fused): IoU + provisional match + NLL + loc loss -------------
__global__ void __launch_bounds__(FT) fused_kernel(
        const float* __restrict__ loc_data,
        const float* __restrict__ conf_data,
        const float* __restrict__ priors,
        const float* __restrict__ gt_boxes,
        const int*   __restrict__ gt_labels) {
    const int b = blockIdx.y;
    const int p0 = blockIdx.x * FP;
    const int tid = threadIdx.x;
    const int warp = tid >> 5;
    const int lane = tid & 31;

    __shared__ float              sconf[FP * NC];
    __shared__ float4             sgt[NOBJ];
    __shared__ int                slab[NOBJ];
    __shared__ unsigned long long skey2[16][NOBJ];
    __shared__ float              snv[FP];
    __shared__ unsigned long long sovgt[FP];

    if (tid < NOBJ) {
        sgt[tid]  = ((const float4*)gt_boxes)[b * NOBJ + tid];
        slab[tid] = gt_labels[b * NOBJ + tid];
    }

    // issue conf loads early; IoU math below hides the DRAM latency
    const float4* src = (const float4*)(conf_data + ((size_t)b * PP + p0) * NC);
    float4 r0 = src[tid];
    float4 r1;
    const bool has1 = tid < (NV4 - FT);   // 460 threads carry a 2nd vector
    if (has1) r1 = src[tid + FT];

    __syncthreads();   // sgt/slab ready (does not wait on the loads above)

    // ---- IoU phase: this warp's 3 priors; lane n = gt n ----
    float4 g = sgt[lane];
    float area_g = (g.z - g.x) * (g.w - g.y);
    unsigned long long mykey = 0ull;
    unsigned myov[3];
    int      myidx[3];
    const int pbase = p0 + warp * 3;
#pragma unroll
    for (int j = 0; j < 3; j++) {
        int p = pbase + j;
        float4 pr = ((const float4*)priors)[p];
        float px1 = pr.x - pr.z * 0.5f, py1 = pr.y - pr.w * 0.5f;
        float px2 = pr.x + pr.z * 0.5f, py2 = pr.y + pr.w * 0.5f;
        float area_p = (px2 - px1) * (py2 - py1);
        float lx = fmaxf(g.x, px1), ly = fmaxf(g.y, py1);
        float rx = fminf(g.z, px2), ry = fminf(g.w, py2);
        float w = fmaxf(rx - lx, 0.f), h = fmaxf(ry - ly, 0.f);
        float inter = w * h;
        float ov = inter / (area_g + area_p - inter);  // IEEE div, matches ref

        unsigned long long key =
            ((unsigned long long)__float_as_uint(ov) << 32) |
            (unsigned long long)(0xFFFFFFFFu - (unsigned)p);
        mykey = (key > mykey) ? key : mykey;

        unsigned ovb = __float_as_uint(ov);           // ov >= 0: uint order ok
        unsigned umax = __reduce_max_sync(0xffffffffu, ovb);
        unsigned bal = __ballot_sync(0xffffffffu, ovb == umax);
        myov[j]  = umax;
        myidx[j] = __ffs(bal) - 1;                    // lowest gt on ties
    }
    skey2[warp][lane] = mykey;

    // ---- land staged conf in smem ----
    float4* sc4 = (float4*)sconf;
    sc4[tid] = r0;
    if (has1) sc4[tid + FT] = r1;
    __syncthreads();

    // warp 0 folds the 16 per-warp gt keys and publishes globally
    if (warp == 0) {
        unsigned long long k = skey2[0][lane];
#pragma unroll
        for (int w2 = 1; w2 < 16; w2++) {
            unsigned long long k2 = skey2[w2][lane];
            k = (k2 > k) ? k2 : k;
        }
        atomicMax(&g_bestkey[b * NOBJ + lane], k);
    }

    // ---- LSE + provisional loss per prior ----
#pragma unroll
    for (int j = 0; j < 3; j++) {
        int q = warp * 3 + j;
        int p = pbase + j;
        const float* row = sconf + q * NC;
        float m, s;
        lse81(row, lane, &m, &s);

        if (lane == 0) {
            float ov = __uint_as_float(myov[j]);
            int   idx = myidx[j];
            int conf_t;
            if (ov < NEG_TH)      conf_t = 0;
            else if (ov < POS_TH) conf_t = -1;
            else                  conf_t = slab[idx] + 1;

            float lse = m + __logf(s);
            int ct = conf_t > 0 ? conf_t : 0;
            float nll = lse - row[ct];
            snv[q]   = (conf_t == 0) ? nll : 0.f;
            sovgt[q] = ((unsigned long long)myov[j] << 32) |
                       (unsigned long long)(unsigned)idx;

            if (conf_t > 0) {
                atomicAdd(&g_loss_c, nll);
                atomicAdd(&g_npos[b], 1);
                atomicAdd(&g_total_pos, 1);
                float4 pr = ((const float4*)priors)[p];
                float4 ld = ((const float4*)loc_data)[(size_t)b * PP + p];
                atomicAdd(&g_loss_l, enc_sl1(pr, sgt[idx], ld));
            }
        }
    }
    __syncthreads();
    if (tid < FP) {   // coalesced final writes
        g_negval[(size_t)b * PP + p0 + tid] = snv[tid];
        g_ovgt[(size_t)b * PP + p0 + tid]   = sovgt[tid];
    }
}

// ---- Kernel 2 (fixup): apply forced matches for each gt's best prior --------
__global__ void __launch_bounds__(1024) fixup_kernel(
        const float* __restrict__ loc_data,
        const float* __restrict__ conf_data,
        const float* __restrict__ priors,
        const float* __restrict__ gt_boxes,
        const int*   __restrict__ gt_labels) {
    const int b = blockIdx.x;
    const int n = threadIdx.x >> 5;     // gt index, one warp each
    const int lane = threadIdx.x & 31;

    // lane i holds gt i's best prior for this batch
    unsigned q_lane = 0xFFFFFFFFu -
        (unsigned)(g_bestkey[b * NOBJ + lane] & 0xFFFFFFFFull);
    unsigned q_n = __shfl_sync(0xffffffffu, q_lane, n);
    unsigned mask = __ballot_sync(0xffffffffu, q_lane == q_n);
    if (31 - __clz(mask) != n) return;  // last-wins: only highest gt patches q

    const int q = (int)q_n;
    const float* row = conf_data + ((size_t)b * PP + q) * NC;
    float m, s;
    lse81(row, lane, &m, &s);

    if (lane == 0) {
        unsigned long long og = g_ovgt[(size_t)b * PP + q];
        float ov_old = __uint_as_float((unsigned)(og >> 32));
        int   idx_old = (int)(unsigned)(og & 0xFFFFFFFFull);

        float lse = m + __logf(s);
        int label_new = gt_labels[b * NOBJ + n];
        float nll_new = lse - row[label_new + 1];
        float4 pr = ((const float4*)priors)[q];
        float4 ld = ((const float4*)loc_data)[(size_t)b * PP + q];
        float4 gtn = ((const float4*)gt_boxes)[b * NOBJ + n];
        float sl1_new = enc_sl1(pr, gtn, ld);

        if (ov_old >= POS_TH) {
            // was provisionally positive with idx_old: swap contributions
            int label_old = gt_labels[b * NOBJ + idx_old];
            float nll_old = lse - row[label_old + 1];
            float4 gto = ((const float4*)gt_boxes)[b * NOBJ + idx_old];
            float sl1_old = enc_sl1(pr, gto, ld);
            atomicAdd(&g_loss_c, nll_new - nll_old);
            atomicAdd(&g_loss_l, sl1_new - sl1_old);
        } else {
            // was background or neutral: becomes positive
            atomicAdd(&g_loss_c, nll_new);
            atomicAdd(&g_loss_l, sl1_new);
            atomicAdd(&g_npos[b], 1);
            atomicAdd(&g_total_pos, 1);
            g_negval[(size_t)b * PP + q] = 0.f;
        }
    }
}

// ---- Kernel 3: hard negative mining (R4 algorithm) + finalize + reset -------
extern __shared__ float sv[];  // PP floats

__device__ __forceinline__ int warp_suffix(int v, int lane) {
#pragma unroll
    for (int off = 1; off < 32; off <<= 1) {
        int t = __shfl_down_sync(0xffffffffu, v, off);
        if (lane + off < 32) v += t;
    }
    return v;
}

__device__ __forceinline__ void find_bin(int* hist, int nb, int Krem,
                                         int tid, int lane, int warpId,
                                         int* s_seg, int* psWstar,
                                         int* psB, int* psK) {
    int nsegs = nb >> 6;
    if (warpId < nsegs) {
        int base = warpId * 64;
        int s = hist[base + lane] + hist[base + 32 + lane];
        s = (int)__reduce_add_sync(0xffffffffu, (unsigned)s);
        if (lane == 0) s_seg[warpId] = s;
    }
    __syncthreads();
    if (tid < 32) {
        int v = (lane < nsegs) ? s_seg[lane] : 0;
        int ssum = warp_suffix(v, lane);
        unsigned bal = __ballot_sync(0xffffffffu, ssum >= Krem);
        int w = 31 - __clz(bal);
        int ssum_w = __shfl_sync(0xffffffffu, ssum, w);
        int v_w    = __shfl_sync(0xffffffffu, v, w);
        if (lane == 0) { *psWstar = w; *psK = Krem - (ssum_w - v_w); }
    }
    __syncthreads();
    if (warpId == *psWstar) {
        int base = warpId * 64;
        int K2 = *psK;
        int h1 = hist[base + 32 + lane];
        int s1 = warp_suffix(h1, lane);
        int tot1 = __shfl_sync(0xffffffffu, s1, 0);
        int bin, Kn;
        if (K2 <= tot1) {
            unsigned bal = __ballot_sync(0xffffffffu, s1 >= K2);
            int l = 31 - __clz(bal);
            bin = base + 32 + l;
            Kn = K2 - (__shfl_sync(0xffffffffu, s1, l) -
                       __shfl_sync(0xffffffffu, h1, l));
        } else {
            int K3 = K2 - tot1;
            int h0 = hist[base + lane];
            int s0 = warp_suffix(h0, lane);
            unsigned bal = __ballot_sync(0xffffffffu, s0 >= K3);
            int l = 31 - __clz(bal);
            bin = base + l;
            Kn = K3 - (__shfl_sync(0xffffffffu, s0, l) -
                       __shfl_sync(0xffffffffu, h0, l));
        }
        if (lane == 0) { *psB = bin; *psK = Kn; }
    }
    __syncthreads();
}

__global__ void __launch_bounds__(1024) mine_kernel(float* __restrict__ out) {
    const int b = blockIdx.x;
    const int tid = threadIdx.x;
    const int lane = tid & 31;
    const int warpId = tid >> 5;
    const int K = min(3 * g_npos[b], PP - 1);

    __shared__ int hist[2048];
    __shared__ int s_seg[32];
    __shared__ int sWstar, sB, sK;
    __shared__ int   s_cnt;
    __shared__ float s_sum;
    __shared__ int   s_last;

    if (K > 0) {
        const float* vals = g_negval + (size_t)b * PP;
        for (int p = tid; p < PP; p += 1024)
            sv[p] = vals[p];

        unsigned prefix = 0, himask = 0;
        int Krem = K;
        const int shifts[3]  = {20, 9, 0};
        const int nbins_a[3] = {2048, 2048, 512};

        for (int st = 0; st < 3; st++) {
            const int shift = shifts[st];
            const int nb = nbins_a[st];
            for (int i = tid; i < nb; i += 1024) hist[i] = 0;
            __syncthreads();
            for (int p = tid; p < PP; p += 1024) {
                unsigned u = __float_as_uint(sv[p]);
                if ((u & himask) == prefix)
                    atomicAdd(&hist[(u >> shift) & (nb - 1)], 1);
            }
            __syncthreads();
            find_bin(hist, nb, Krem, tid, lane, warpId, s_seg, &sWstar, &sB, &sK);
            prefix |= ((unsigned)sB) << shift;
            himask |= ((unsigned)(nb - 1)) << shift;
            Krem = sK;
            __syncthreads();
        }

        if (tid == 0) { s_cnt = 0; s_sum = 0.f; }
        __syncthreads();
        float t = __uint_as_float(prefix);
        int cgt = 0;
        float sum = 0.f;
        for (int p = tid; p < PP; p += 1024) {
            float v = sv[p];
            if (__float_as_uint(v) > prefix) { cgt++; sum += v; }
        }
#pragma unroll
        for (int off = 16; off > 0; off >>= 1) {
            cgt += __shfl_down_sync(0xffffffffu, cgt, off);
            sum += __shfl_down_sync(0xffffffffu, sum, off);
        }
        if (lane == 0) { atomicAdd(&s_cnt, cgt); atomicAdd(&s_sum, sum); }
        __syncthreads();
        if (tid == 0)
            atomicAdd(&g_loss_c, s_sum + (float)(K - s_cnt) * t);
    }

    // finalize: last block writes out and resets state for next replay
    __syncthreads();
    if (tid == 0) {
        __threadfence();
        s_last = (atomicAdd(&g_done, 1) == BB - 1) ? 1 : 0;
    }
    __syncthreads();
    if (s_last) {
        if (tid == 0) {
            float lc = atomicAdd(&g_loss_c, 0.f);
            float ll = atomicAdd(&g_loss_l, 0.f);
            int   tp = atomicAdd(&g_total_pos, 0);
            float N = (float)max(tp, 1);
            out[0] = ll / N;
            out[1] = lc / N;
            g_loss_l = 0.f;
            g_loss_c = 0.f;
            g_total_pos = 0;
            g_done = 0;
        }
        if (tid < BB) g_npos[tid] = 0;
        if (tid < BB * NOBJ) g_bestkey[tid] = 0ull;
    }
}

extern "C" void kernel_launch(void* const* d_in, const int* in_sizes, int n_in,
                              void* d_out, int out_size) {
    const float* loc_data  = (const float*)d_in[0];
    const float* conf_data = (const float*)d_in[1];
    const float* priors    = (const float*)d_in[2];
    const float* gt_boxes  = (const float*)d_in[3];
    const int*   gt_labels = (const int*)d_in[4];
    float* out = (float*)d_out;

    cudaFuncSetAttribute(mine_kernel,
                         cudaFuncAttributeMaxDynamicSharedMemorySize,
                         PP * (int)sizeof(float));

    dim3 gridF(PP / FP, BB);
    fused_kernel<<<gridF, FT>>>(loc_data, conf_data, priors, gt_boxes, gt_labels);
    fixup_kernel<<<BB, 1024>>>(loc_data, conf_data, priors, gt_boxes, gt_labels);
    mine_kernel<<<BB, 1024, PP * (int)sizeof(float)>>>(out);
}